// round 7
// baseline (speedup 1.0000x reference)
#include <cuda_runtime.h>
#include <cuda_bf16.h>

// Scratch (no cudaMalloc allowed). Shapes: B=1024 (<=4096), E=50000 (<=65536).
__device__ float g_hr[4096];      // hr_part[b] + bias
__device__ float g_tail[65536];   // fallback path only

#define THREADS 256
#define ETILE   128   // e-columns per CTA in the fused kernel (32 float4)

// ---------------------------------------------------------------------------
// Kernel 1 (tiny): hr_part[b] = hr[b,:].W1 + bias, warp per row.
// Also zero-fills trailing [zstart, total) of output.
// ---------------------------------------------------------------------------
__global__ void hr_dots_kernel(const float* __restrict__ hr,
                               const float* __restrict__ W,
                               const float* __restrict__ bias,
                               int B, int C,
                               float* __restrict__ out,
                               long long zstart, long long total) {
    int gid  = blockIdx.x * blockDim.x + threadIdx.x;
    long long zi = zstart + (long long)gid;
    if (zi < total) out[zi] = 0.0f;

    int warp = gid >> 5;
    int lane = threadIdx.x & 31;
    if (warp >= B) return;

    const float* row = hr + (size_t)warp * C;
    float acc = 0.0f;
    if ((C & 3) == 0) {
        const float4* r4 = reinterpret_cast<const float4*>(row);
        const float4* w4 = reinterpret_cast<const float4*>(W);
        int C4 = C >> 2;
        for (int k = lane; k < C4; k += 32) {
            float4 a = __ldg(r4 + k);
            float4 b = __ldg(w4 + k);
            acc += a.x * b.x + a.y * b.y + a.z * b.z + a.w * b.w;
        }
    } else {
        for (int k = lane; k < C; k += 32)
            acc += __ldg(row + k) * __ldg(W + k);
    }
#pragma unroll
    for (int off = 16; off; off >>= 1)
        acc += __shfl_xor_sync(0xffffffffu, acc, off);
    if (lane == 0) g_hr[warp] = acc + bias[0];
}

// ---------------------------------------------------------------------------
// Kernel 2 (fused): per CTA, compute 128 tail dots into SMEM (no global
// round-trip), then broadcast-write out[b, e-tile] for all b.
// LTS traffic = tail read (once) + output write (once) only.
// ---------------------------------------------------------------------------
__global__ __launch_bounds__(THREADS)
void fused_tail_bcast_kernel(const float* __restrict__ tail,
                             const float* __restrict__ W2,
                             float* __restrict__ out,
                             int B, int E, int C) {
    __shared__ float sh_t[ETILE];
    __shared__ float sh_h[4096];

    int tid = threadIdx.x;
    int w = tid >> 5;          // warp 0..7
    int l = tid & 31;          // lane
    int e0 = blockIdx.x * ETILE;

    // Stage hr_part into shared (4 KB; L2-hot after first CTA).
    for (int b = tid; b < B; b += THREADS)
        sh_h[b] = g_hr[b];

    // Phase 1: warp-per-row tail dots for this e-tile (streaming loads).
    int C4 = C >> 2;
    const float4* w4 = reinterpret_cast<const float4*>(W2);
    for (int r = w; r < ETILE; r += 8) {
        int e = e0 + r;
        if (e < E) {
            const float4* r4 =
                reinterpret_cast<const float4*>(tail + (size_t)e * C);
            float acc = 0.0f;
            for (int k = l; k < C4; k += 32) {
                float4 a = __ldcs(r4 + k);   // stream: don't pollute L2
                float4 b = __ldg(w4 + k);
                acc += a.x * b.x + a.y * b.y + a.z * b.z + a.w * b.w;
            }
#pragma unroll
            for (int off = 16; off; off >>= 1)
                acc += __shfl_xor_sync(0xffffffffu, acc, off);
            if (l == 0) sh_t[r] = acc;
        }
    }
    __syncthreads();

    // Phase 2: broadcast write. Thread (w,l) owns float4 column e0+4l,
    // iterates b = w, w+8, ... (B/8 iterations, 1 streaming store each).
    int e = e0 + 4 * l;
    if (e >= E) return;   // (E%4==0 on this path, so full-float4 guard)
    float4 t = *reinterpret_cast<const float4*>(sh_t + 4 * l);
    float* base = out + e;
#pragma unroll 4
    for (int b = w; b < B; b += 8) {
        float h = sh_h[b];
        float4 r = make_float4(t.x + h, t.y + h, t.z + h, t.w + h);
        __stcs(reinterpret_cast<float4*>(base + (size_t)b * E), r);
    }
}

// ---------------------------------------------------------------------------
// Generic fallback (odd shapes): dots over B+E rows, then scalar broadcast.
// ---------------------------------------------------------------------------
__global__ void dots_kernel(const float* __restrict__ hr,
                            const float* __restrict__ tail,
                            const float* __restrict__ W,
                            const float* __restrict__ bias,
                            int B, int E, int C,
                            float* __restrict__ out,
                            long long zstart, long long total) {
    int gid  = blockIdx.x * blockDim.x + threadIdx.x;
    int warp = gid >> 5;
    int lane = threadIdx.x & 31;
    long long zi = zstart + (long long)gid;
    if (zi < total) out[zi] = 0.0f;
    if (warp >= B + E) return;
    const float* row; const float* w;
    if (warp < B) { row = hr   + (size_t)warp * C;       w = W;     }
    else          { row = tail + (size_t)(warp - B) * C; w = W + C; }
    float acc = 0.0f;
    for (int k = lane; k < C; k += 32)
        acc += __ldg(row + k) * __ldg(w + k);
#pragma unroll
    for (int off = 16; off; off >>= 1)
        acc += __shfl_xor_sync(0xffffffffu, acc, off);
    if (lane == 0) {
        if (warp < B) g_hr[warp] = acc + bias[0];
        else          g_tail[warp - B] = acc;
    }
}

__global__ void bcast_scalar_kernel(float* __restrict__ out, int E) {
    int e = blockIdx.x * blockDim.x + threadIdx.x;
    if (e >= E) return;
    int b = blockIdx.y;
    out[(size_t)b * E + e] = g_hr[b] + g_tail[e];
}

extern "C" void kernel_launch(void* const* d_in, const int* in_sizes, int n_in,
                              void* d_out, int out_size) {
    const float* hr   = (const float*)d_in[0];  // [B, C]
    const float* tail = (const float*)d_in[1];  // [E, C]
    const float* W    = (const float*)d_in[2];  // [1, 2C]
    const float* bias = (const float*)d_in[3];  // [1]
    float* out = (float*)d_out;

    int C = in_sizes[2] / 2;
    int B = in_sizes[0] / C;
    int E = in_sizes[1] / C;

    long long BE    = (long long)B * (long long)E;
    long long total = (long long)out_size;

    bool fast = ((C & 3) == 0) && ((E & 3) == 0) && (B <= 4096);

    if (fast) {
        // 1) hr dots (+ trailing zero-fill)
        {
            long long lanes = (long long)B * 32;
            long long extra = (total > BE) ? (total - BE) : 0;
            if (extra > lanes) lanes = extra;
            int blocks = (int)((lanes + THREADS - 1) / THREADS);
            hr_dots_kernel<<<blocks, THREADS>>>(hr, W, bias, B, C,
                                                out, BE, total);
        }
        // 2) fused tail dots + broadcast
        {
            int blocks = (E + ETILE - 1) / ETILE;
            fused_tail_bcast_kernel<<<blocks, THREADS>>>(tail, W + C, out,
                                                         B, E, C);
        }
    } else {
        {
            int rows = B + E;
            long long lanes = (long long)rows * 32;
            long long extra = (total > BE) ? (total - BE) : 0;
            if (extra > lanes) lanes = extra;
            int blocks = (int)((lanes + THREADS - 1) / THREADS);
            dots_kernel<<<blocks, THREADS>>>(hr, tail, W, bias, B, E, C,
                                             out, BE, total);
        }
        {
            dim3 grid((E + THREADS - 1) / THREADS, B);
            bcast_scalar_kernel<<<grid, THREADS>>>(out, E);
        }
    }
}

// round 8
// speedup vs baseline: 1.1414x; 1.1414x over previous
#include <cuda_runtime.h>
#include <cuda_bf16.h>

// Scratch (no cudaMalloc allowed). Shapes: B=1024 (<=4096), E=50000 (<=65536).
__device__ float g_hr[4096];        // hr_part[b] + bias
__device__ float g_tail[65536];     // tail_part[e]
__device__ unsigned int g_bar = 0;  // monotonic grid barrier counter

#define THREADS 256
#define BTILE   16

// ---------------------------------------------------------------------------
// Persistent kernel: phase 1 computes all row dots (warp per row, grid
// stride), grid barrier, phase 2 does the broadcast write (BTILE b-rows per
// work item). Single launch -> no inter-kernel gap; both phases have ~4700
// warps so the LTS path stays saturated.
// ---------------------------------------------------------------------------
__global__ __launch_bounds__(THREADS, 4)
void persistent_kernel(const float* __restrict__ hr,
                       const float* __restrict__ tail,
                       const float* __restrict__ W,     // [2C]: W1 | W2
                       const float* __restrict__ bias,
                       int B, int E, int C,
                       float* __restrict__ out,
                       long long zstart, long long total,
                       int nblocks) {
    const int tid  = threadIdx.x;
    const int gid  = blockIdx.x * THREADS + tid;
    const int gsz  = nblocks * THREADS;
    const int lane = tid & 31;
    const int gwarp  = gid >> 5;
    const int nwarps = gsz >> 5;

    // Trailing zero-fill of output (reference returns (scores, 0)).
    for (long long zi = zstart + gid; zi < total; zi += gsz)
        out[zi] = 0.0f;

    // ---- Phase 1: dots. row < B -> g_hr (+bias), else g_tail. ----
    const int rows = B + E;
    const int C4 = C >> 2;
    for (int r = gwarp; r < rows; r += nwarps) {
        const float4* row4;
        const float4* w4;
        if (r < B) {
            row4 = reinterpret_cast<const float4*>(hr + (size_t)r * C);
            w4   = reinterpret_cast<const float4*>(W);
        } else {
            row4 = reinterpret_cast<const float4*>(tail + (size_t)(r - B) * C);
            w4   = reinterpret_cast<const float4*>(W + C);
        }
        float acc = 0.0f;
        for (int k = lane; k < C4; k += 32) {
            float4 a = __ldcs(row4 + k);   // streamed: read-once data
            float4 b = __ldg(w4 + k);
            acc += a.x * b.x + a.y * b.y + a.z * b.z + a.w * b.w;
        }
#pragma unroll
        for (int off = 16; off; off >>= 1)
            acc += __shfl_xor_sync(0xffffffffu, acc, off);
        if (lane == 0) {
            if (r < B) g_hr[r] = acc + bias[0];
            else       g_tail[r - B] = acc;
        }
    }

    // ---- Grid barrier (monotonic counter: replay-safe, no reset race). ----
    __syncthreads();
    __threadfence();
    if (tid == 0) {
        unsigned ticket = atomicAdd(&g_bar, 1u);
        unsigned target = (ticket / (unsigned)nblocks + 1u) * (unsigned)nblocks;
        while (*((volatile unsigned*)&g_bar) < target)
            __nanosleep(64);
    }
    __syncthreads();
    __threadfence();

    // ---- Phase 2: out[b, e] = g_hr[b] + g_tail[e], BTILE rows per item. ----
    const int E4  = E >> 2;
    const int nbt = (B + BTILE - 1) / BTILE;
    const long long items = (long long)nbt * E4;
    const long long rowstride4 = (long long)(E >> 2);

    for (long long it = gid; it < items; it += gsz) {
        int bt = (int)(it / E4);
        int e4 = (int)(it - (long long)bt * E4);
        int b0 = bt * BTILE;

        float4 t = __ldg(reinterpret_cast<const float4*>(g_tail) + e4);
        float4* base = reinterpret_cast<float4*>(out + (size_t)b0 * E) + e4;

        int nb = B - b0;
        if (nb >= BTILE) {
#pragma unroll
            for (int i = 0; i < BTILE; i++) {
                float h = __ldg(g_hr + b0 + i);
                float4 r = make_float4(t.x + h, t.y + h, t.z + h, t.w + h);
                __stcs(base + (long long)i * rowstride4, r);
            }
        } else {
            for (int i = 0; i < nb; i++) {
                float h = __ldg(g_hr + b0 + i);
                float4 r = make_float4(t.x + h, t.y + h, t.z + h, t.w + h);
                __stcs(base + (long long)i * rowstride4, r);
            }
        }
    }
}

// ---------------------------------------------------------------------------
// Generic fallback (odd shapes): dots over B+E rows, then scalar broadcast.
// ---------------------------------------------------------------------------
__global__ void dots_kernel(const float* __restrict__ hr,
                            const float* __restrict__ tail,
                            const float* __restrict__ W,
                            const float* __restrict__ bias,
                            int B, int E, int C,
                            float* __restrict__ out,
                            long long zstart, long long total) {
    int gid  = blockIdx.x * blockDim.x + threadIdx.x;
    int warp = gid >> 5;
    int lane = threadIdx.x & 31;
    long long zi = zstart + (long long)gid;
    if (zi < total) out[zi] = 0.0f;
    if (warp >= B + E) return;
    const float* row; const float* w;
    if (warp < B) { row = hr   + (size_t)warp * C;       w = W;     }
    else          { row = tail + (size_t)(warp - B) * C; w = W + C; }
    float acc = 0.0f;
    for (int k = lane; k < C; k += 32)
        acc += __ldg(row + k) * __ldg(w + k);
#pragma unroll
    for (int off = 16; off; off >>= 1)
        acc += __shfl_xor_sync(0xffffffffu, acc, off);
    if (lane == 0) {
        if (warp < B) g_hr[warp] = acc + bias[0];
        else          g_tail[warp - B] = acc;
    }
}

__global__ void bcast_scalar_kernel(float* __restrict__ out, int E) {
    int e = blockIdx.x * blockDim.x + threadIdx.x;
    if (e >= E) return;
    int b = blockIdx.y;
    out[(size_t)b * E + e] = g_hr[b] + g_tail[e];
}

extern "C" void kernel_launch(void* const* d_in, const int* in_sizes, int n_in,
                              void* d_out, int out_size) {
    const float* hr   = (const float*)d_in[0];  // [B, C]
    const float* tail = (const float*)d_in[1];  // [E, C]
    const float* W    = (const float*)d_in[2];  // [1, 2C]
    const float* bias = (const float*)d_in[3];  // [1]
    float* out = (float*)d_out;

    int C = in_sizes[2] / 2;
    int B = in_sizes[0] / C;
    int E = in_sizes[1] / C;

    long long BE    = (long long)B * (long long)E;
    long long total = (long long)out_size;

    bool fast = ((C & 3) == 0) && ((E & 3) == 0) && (B <= 4096) && (E <= 65536);

    if (fast) {
        // Guaranteed-resident grid: SMs x min(max-active-blocks, 4).
        int sm_count = 0;
        cudaDeviceGetAttribute(&sm_count, cudaDevAttrMultiProcessorCount, 0);
        if (sm_count <= 0) sm_count = 148;
        int max_blk = 0;
        cudaOccupancyMaxActiveBlocksPerMultiprocessor(
            &max_blk, persistent_kernel, THREADS, 0);
        if (max_blk <= 0) max_blk = 1;
        if (max_blk > 4) max_blk = 4;
        int nblocks = sm_count * max_blk;

        persistent_kernel<<<nblocks, THREADS>>>(hr, tail, W, bias, B, E, C,
                                                out, BE, total, nblocks);
    } else {
        {
            int rows = B + E;
            long long lanes = (long long)rows * 32;
            long long extra = (total > BE) ? (total - BE) : 0;
            if (extra > lanes) lanes = extra;
            int blocks = (int)((lanes + THREADS - 1) / THREADS);
            dots_kernel<<<blocks, THREADS>>>(hr, tail, W, bias, B, E, C,
                                             out, BE, total);
        }
        {
            dim3 grid((E + THREADS - 1) / THREADS, B);
            bcast_scalar_kernel<<<grid, THREADS>>>(out, E);
        }
    }
}

// round 9
// speedup vs baseline: 1.1561x; 1.0128x over previous
#include <cuda_runtime.h>
#include <cuda_bf16.h>

// Scratch (no cudaMalloc allowed). Shapes: B=1024 (<=4096), E=50000 (<=65536).
__device__ float g_hr[4096];      // hr_part[b] + bias
__device__ float g_tail[65536];   // tail_part[e]

#define THREADS 256
#define BTILE   32   // b-rows per bcast CTA (gridDim.y = ceil(B/BTILE))

// ---------------------------------------------------------------------------
// Fused warp-per-row dot kernel over B+E rows (validated R5 shape).
//   row <  B : g_hr[row]     = hr[row,:]    . W1 + bias
//   row >= B : g_tail[row-B] = tail[row-B,:]. W2
// Also zero-fills the trailing [zstart, total) region of the output.
// ---------------------------------------------------------------------------
__global__ void dots_kernel(const float* __restrict__ hr,
                            const float* __restrict__ tail,
                            const float* __restrict__ W,   // [2C]: W1 | W2
                            const float* __restrict__ bias,
                            int B, int E, int C,
                            float* __restrict__ out,
                            long long zstart, long long total) {
    int gid  = blockIdx.x * blockDim.x + threadIdx.x;
    int warp = gid >> 5;
    int lane = threadIdx.x & 31;

    long long zi = zstart + (long long)gid;
    if (zi < total) out[zi] = 0.0f;

    int rows = B + E;
    if (warp >= rows) return;

    const float* row;
    const float* w;
    if (warp < B) { row = hr   + (size_t)warp * C;       w = W;     }
    else          { row = tail + (size_t)(warp - B) * C; w = W + C; }

    float acc = 0.0f;
    if ((C & 3) == 0) {
        const float4* row4 = reinterpret_cast<const float4*>(row);
        const float4* w4   = reinterpret_cast<const float4*>(w);
        int C4 = C >> 2;
#pragma unroll 4
        for (int k = lane; k < C4; k += 32) {
            float4 a = __ldcs(row4 + k);   // read-once: stream past L2
            float4 b = __ldg(w4 + k);      // W: tiny, keep cached
            acc += a.x * b.x + a.y * b.y + a.z * b.z + a.w * b.w;
        }
    } else {
        for (int k = lane; k < C; k += 32)
            acc += __ldg(row + k) * __ldg(w + k);
    }
#pragma unroll
    for (int off = 16; off; off >>= 1)
        acc += __shfl_xor_sync(0xffffffffu, acc, off);

    if (lane == 0) {
        if (warp < B) g_hr[warp] = acc + bias[0];
        else          g_tail[warp - B] = acc;
    }
}

// ---------------------------------------------------------------------------
// Broadcast write, b-tiled: each thread loads tail4[e4] ONCE and streams it
// (plus per-row h from shared) to BTILE consecutive b-rows.
// L2 read traffic for g_tail drops to 205/BTILE MB; 32 independent stores
// per thread keep the store pipe full.
// ---------------------------------------------------------------------------
__global__ __launch_bounds__(THREADS)
void bcast_vec_kernel(float* __restrict__ out, int E4, long long E, int B) {
    __shared__ float sh[BTILE];
    int b0 = blockIdx.y * BTILE;
    if (threadIdx.x < BTILE) {
        int b = b0 + threadIdx.x;
        sh[threadIdx.x] = (b < B) ? g_hr[b] : 0.0f;
    }
    __syncthreads();

    int e4 = blockIdx.x * blockDim.x + threadIdx.x;
    if (e4 >= E4) return;

    float4 t = __ldg(reinterpret_cast<const float4*>(g_tail) + e4);

    float4* base = reinterpret_cast<float4*>(out + (size_t)b0 * E) + e4;
    long long rowstride4 = E >> 2;

    int nb = B - b0;
    if (nb >= BTILE) {
#pragma unroll
        for (int i = 0; i < BTILE; i++) {
            float h = sh[i];
            float4 r = make_float4(t.x + h, t.y + h, t.z + h, t.w + h);
            __stcs(base + (long long)i * rowstride4, r);
        }
    } else {
        for (int i = 0; i < nb; i++) {
            float h = sh[i];
            float4 r = make_float4(t.x + h, t.y + h, t.z + h, t.w + h);
            __stcs(base + (long long)i * rowstride4, r);
        }
    }
}

// Scalar fallback for E % 4 != 0.
__global__ void bcast_scalar_kernel(float* __restrict__ out, int E) {
    int e = blockIdx.x * blockDim.x + threadIdx.x;
    if (e >= E) return;
    int b = blockIdx.y;
    out[(size_t)b * E + e] = g_hr[b] + g_tail[e];
}

extern "C" void kernel_launch(void* const* d_in, const int* in_sizes, int n_in,
                              void* d_out, int out_size) {
    const float* hr   = (const float*)d_in[0];  // [B, C]
    const float* tail = (const float*)d_in[1];  // [E, C]
    const float* W    = (const float*)d_in[2];  // [1, 2C]
    const float* bias = (const float*)d_in[3];  // [1]
    float* out = (float*)d_out;

    int C = in_sizes[2] / 2;
    int B = in_sizes[0] / C;
    int E = in_sizes[1] / C;

    long long BE    = (long long)B * (long long)E;
    long long total = (long long)out_size;

    // 1) fused hr+tail dots (+ trailing zero-fill)
    {
        int rows = B + E;
        long long lanes = (long long)rows * 32;
        long long extra = (total > BE) ? (total - BE) : 0;
        if (extra > lanes) lanes = extra;
        int blocks = (int)((lanes + THREADS - 1) / THREADS);
        dots_kernel<<<blocks, THREADS>>>(hr, tail, W, bias, B, E, C,
                                         out, BE, total);
    }

    // 2) broadcast sum -> out
    if ((E & 3) == 0) {
        int E4 = E >> 2;
        dim3 grid((E4 + THREADS - 1) / THREADS, (B + BTILE - 1) / BTILE);
        bcast_vec_kernel<<<grid, THREADS>>>(out, E4, (long long)E, B);
    } else {
        dim3 grid((E + THREADS - 1) / THREADS, B);
        bcast_scalar_kernel<<<grid, THREADS>>>(out, E);
    }
}

// round 10
// speedup vs baseline: 1.1995x; 1.0376x over previous
#include <cuda_runtime.h>
#include <cuda_bf16.h>

// Scratch (no cudaMalloc allowed). Shapes: B=1024 (<=4096), E=50000 (<=65536).
__device__ float g_hr[4096];      // hr_part[b] + bias
__device__ float g_tail[65536];   // tail_part[e]

#define THREADS 256
#define BTILE   32   // b-rows per bcast CTA (gridDim.y = ceil(B/BTILE))

// ---------------------------------------------------------------------------
// Fused warp-per-row dot kernel over B+E rows — exact R6 configuration
// (__ldg row reads; no unroll pragma), which measured fastest.
//   row <  B : g_hr[row]     = hr[row,:]    . W1 + bias
//   row >= B : g_tail[row-B] = tail[row-B,:]. W2
// Also zero-fills the trailing [zstart, total) region of the output.
// ---------------------------------------------------------------------------
__global__ void dots_kernel(const float* __restrict__ hr,
                            const float* __restrict__ tail,
                            const float* __restrict__ W,   // [2C]: W1 | W2
                            const float* __restrict__ bias,
                            int B, int E, int C,
                            float* __restrict__ out,
                            long long zstart, long long total) {
    int gid  = blockIdx.x * blockDim.x + threadIdx.x;
    int warp = gid >> 5;
    int lane = threadIdx.x & 31;

    long long zi = zstart + (long long)gid;
    if (zi < total) out[zi] = 0.0f;

    int rows = B + E;
    if (warp >= rows) return;

    const float* row;
    const float* w;
    if (warp < B) { row = hr   + (size_t)warp * C;       w = W;     }
    else          { row = tail + (size_t)(warp - B) * C; w = W + C; }

    float acc = 0.0f;
    if ((C & 3) == 0) {
        const float4* row4 = reinterpret_cast<const float4*>(row);
        const float4* w4   = reinterpret_cast<const float4*>(w);
        int C4 = C >> 2;
        for (int k = lane; k < C4; k += 32) {
            float4 a = __ldg(row4 + k);
            float4 b = __ldg(w4 + k);
            acc += a.x * b.x + a.y * b.y + a.z * b.z + a.w * b.w;
        }
    } else {
        for (int k = lane; k < C; k += 32)
            acc += __ldg(row + k) * __ldg(w + k);
    }
#pragma unroll
    for (int off = 16; off; off >>= 1)
        acc += __shfl_xor_sync(0xffffffffu, acc, off);

    if (lane == 0) {
        if (warp < B) g_hr[warp] = acc + bias[0];
        else          g_tail[warp - B] = acc;
    }
}

// ---------------------------------------------------------------------------
// Broadcast write, b-tiled (R8 configuration, measured 31.6us = LTS wall):
// each thread loads tail4[e4] ONCE and streams it (+ per-row h from shared)
// to BTILE consecutive b-rows with independent __stcs stores.
// ---------------------------------------------------------------------------
__global__ __launch_bounds__(THREADS)
void bcast_vec_kernel(float* __restrict__ out, int E4, long long E, int B) {
    __shared__ float sh[BTILE];
    int b0 = blockIdx.y * BTILE;
    if (threadIdx.x < BTILE) {
        int b = b0 + threadIdx.x;
        sh[threadIdx.x] = (b < B) ? g_hr[b] : 0.0f;
    }
    __syncthreads();

    int e4 = blockIdx.x * blockDim.x + threadIdx.x;
    if (e4 >= E4) return;

    float4 t = __ldg(reinterpret_cast<const float4*>(g_tail) + e4);

    float4* base = reinterpret_cast<float4*>(out + (size_t)b0 * E) + e4;
    long long rowstride4 = E >> 2;

    int nb = B - b0;
    if (nb >= BTILE) {
#pragma unroll
        for (int i = 0; i < BTILE; i++) {
            float h = sh[i];
            float4 r = make_float4(t.x + h, t.y + h, t.z + h, t.w + h);
            __stcs(base + (long long)i * rowstride4, r);
        }
    } else {
        for (int i = 0; i < nb; i++) {
            float h = sh[i];
            float4 r = make_float4(t.x + h, t.y + h, t.z + h, t.w + h);
            __stcs(base + (long long)i * rowstride4, r);
        }
    }
}

// Scalar fallback for E % 4 != 0.
__global__ void bcast_scalar_kernel(float* __restrict__ out, int E) {
    int e = blockIdx.x * blockDim.x + threadIdx.x;
    if (e >= E) return;
    int b = blockIdx.y;
    out[(size_t)b * E + e] = g_hr[b] + g_tail[e];
}

extern "C" void kernel_launch(void* const* d_in, const int* in_sizes, int n_in,
                              void* d_out, int out_size) {
    const float* hr   = (const float*)d_in[0];  // [B, C]
    const float* tail = (const float*)d_in[1];  // [E, C]
    const float* W    = (const float*)d_in[2];  // [1, 2C]
    const float* bias = (const float*)d_in[3];  // [1]
    float* out = (float*)d_out;

    int C = in_sizes[2] / 2;
    int B = in_sizes[0] / C;
    int E = in_sizes[1] / C;

    long long BE    = (long long)B * (long long)E;
    long long total = (long long)out_size;

    // 1) fused hr+tail dots (+ trailing zero-fill)
    {
        int rows = B + E;
        long long lanes = (long long)rows * 32;
        long long extra = (total > BE) ? (total - BE) : 0;
        if (extra > lanes) lanes = extra;
        int blocks = (int)((lanes + THREADS - 1) / THREADS);
        dots_kernel<<<blocks, THREADS>>>(hr, tail, W, bias, B, E, C,
                                         out, BE, total);
    }

    // 2) broadcast sum -> out
    if ((E & 3) == 0) {
        int E4 = E >> 2;
        dim3 grid((E4 + THREADS - 1) / THREADS, (B + BTILE - 1) / BTILE);
        bcast_vec_kernel<<<grid, THREADS>>>(out, E4, (long long)E, B);
    } else {
        dim3 grid((E + THREADS - 1) / THREADS, B);
        bcast_scalar_kernel<<<grid, THREADS>>>(out, E);
    }
}

// round 11
// speedup vs baseline: 1.2442x; 1.0372x over previous
#include <cuda_runtime.h>
#include <cuda_bf16.h>

// Scratch (no cudaMalloc allowed). Shapes: B=1024 (<=4096), E=50000 (<=65536).
__device__ float g_hr[4096];      // hr_part[b] + bias
__device__ float g_tail[65536];   // tail_part[e]

#define THREADS 256
#define BTILE   16   // b-rows per bcast CTA (plateau midpoint: low re-reads, high occ)

// ---------------------------------------------------------------------------
// Fused warp-per-row dot kernel over B+E rows.
//   row <  B : g_hr[row]     = hr[row,:]    . W1 + bias
//   row >= B : g_tail[row-B] = tail[row-B,:]. W2
// C==512 fast path: batch all 8 LDG.128s up front (MLP_p1=8).
// Also zero-fills the trailing [zstart, total) region of the output.
// ---------------------------------------------------------------------------
__global__ void dots_kernel(const float* __restrict__ hr,
                            const float* __restrict__ tail,
                            const float* __restrict__ W,   // [2C]: W1 | W2
                            const float* __restrict__ bias,
                            int B, int E, int C,
                            float* __restrict__ out,
                            long long zstart, long long total) {
    int gid  = blockIdx.x * blockDim.x + threadIdx.x;
    int warp = gid >> 5;
    int lane = threadIdx.x & 31;

    long long zi = zstart + (long long)gid;
    if (zi < total) out[zi] = 0.0f;

    int rows = B + E;
    if (warp >= rows) return;

    const float* row;
    const float* w;
    if (warp < B) { row = hr   + (size_t)warp * C;       w = W;     }
    else          { row = tail + (size_t)(warp - B) * C; w = W + C; }

    float acc = 0.0f;
    if (C == 512) {
        // Exactly 4 float4 iterations per lane: batch all loads first.
        const float4* r4 = reinterpret_cast<const float4*>(row);
        const float4* w4 = reinterpret_cast<const float4*>(w);
        float4 a0 = __ldg(r4 + lane);
        float4 a1 = __ldg(r4 + lane + 32);
        float4 a2 = __ldg(r4 + lane + 64);
        float4 a3 = __ldg(r4 + lane + 96);
        float4 b0 = __ldg(w4 + lane);
        float4 b1 = __ldg(w4 + lane + 32);
        float4 b2 = __ldg(w4 + lane + 64);
        float4 b3 = __ldg(w4 + lane + 96);
        float s0 = a0.x * b0.x + a0.y * b0.y + a0.z * b0.z + a0.w * b0.w;
        float s1 = a1.x * b1.x + a1.y * b1.y + a1.z * b1.z + a1.w * b1.w;
        float s2 = a2.x * b2.x + a2.y * b2.y + a2.z * b2.z + a2.w * b2.w;
        float s3 = a3.x * b3.x + a3.y * b3.y + a3.z * b3.z + a3.w * b3.w;
        acc = (s0 + s1) + (s2 + s3);
    } else if ((C & 3) == 0) {
        const float4* r4 = reinterpret_cast<const float4*>(row);
        const float4* w4 = reinterpret_cast<const float4*>(w);
        int C4 = C >> 2;
        for (int k = lane; k < C4; k += 32) {
            float4 a = __ldg(r4 + k);
            float4 b = __ldg(w4 + k);
            acc += a.x * b.x + a.y * b.y + a.z * b.z + a.w * b.w;
        }
    } else {
        for (int k = lane; k < C; k += 32)
            acc += __ldg(row + k) * __ldg(w + k);
    }
#pragma unroll
    for (int off = 16; off; off >>= 1)
        acc += __shfl_xor_sync(0xffffffffu, acc, off);

    if (lane == 0) {
        if (warp < B) g_hr[warp] = acc + bias[0];
        else          g_tail[warp - B] = acc;
    }
}

// ---------------------------------------------------------------------------
// Broadcast write, b-tiled: each thread loads tail4[e4] ONCE and streams it
// (plus per-row h from shared) to BTILE consecutive b-rows via __stcs.
// ---------------------------------------------------------------------------
__global__ __launch_bounds__(THREADS)
void bcast_vec_kernel(float* __restrict__ out, int E4, long long E, int B) {
    __shared__ float sh[BTILE];
    int b0 = blockIdx.y * BTILE;
    if (threadIdx.x < BTILE) {
        int b = b0 + threadIdx.x;
        sh[threadIdx.x] = (b < B) ? g_hr[b] : 0.0f;
    }
    __syncthreads();

    int e4 = blockIdx.x * blockDim.x + threadIdx.x;
    if (e4 >= E4) return;

    float4 t = __ldg(reinterpret_cast<const float4*>(g_tail) + e4);

    float4* base = reinterpret_cast<float4*>(out + (size_t)b0 * E) + e4;
    long long rowstride4 = E >> 2;

    int nb = B - b0;
    if (nb >= BTILE) {
#pragma unroll
        for (int i = 0; i < BTILE; i++) {
            float h = sh[i];
            float4 r = make_float4(t.x + h, t.y + h, t.z + h, t.w + h);
            __stcs(base + (long long)i * rowstride4, r);
        }
    } else {
        for (int i = 0; i < nb; i++) {
            float h = sh[i];
            float4 r = make_float4(t.x + h, t.y + h, t.z + h, t.w + h);
            __stcs(base + (long long)i * rowstride4, r);
        }
    }
}

// Scalar fallback for E % 4 != 0.
__global__ void bcast_scalar_kernel(float* __restrict__ out, int E) {
    int e = blockIdx.x * blockDim.x + threadIdx.x;
    if (e >= E) return;
    int b = blockIdx.y;
    out[(size_t)b * E + e] = g_hr[b] + g_tail[e];
}

extern "C" void kernel_launch(void* const* d_in, const int* in_sizes, int n_in,
                              void* d_out, int out_size) {
    const float* hr   = (const float*)d_in[0];  // [B, C]
    const float* tail = (const float*)d_in[1];  // [E, C]
    const float* W    = (const float*)d_in[2];  // [1, 2C]
    const float* bias = (const float*)d_in[3];  // [1]
    float* out = (float*)d_out;

    int C = in_sizes[2] / 2;
    int B = in_sizes[0] / C;
    int E = in_sizes[1] / C;

    long long BE    = (long long)B * (long long)E;
    long long total = (long long)out_size;

    // 1) fused hr+tail dots (+ trailing zero-fill)
    {
        int rows = B + E;
        long long lanes = (long long)rows * 32;
        long long extra = (total > BE) ? (total - BE) : 0;
        if (extra > lanes) lanes = extra;
        int blocks = (int)((lanes + THREADS - 1) / THREADS);
        dots_kernel<<<blocks, THREADS>>>(hr, tail, W, bias, B, E, C,
                                         out, BE, total);
    }

    // 2) broadcast sum -> out
    if ((E & 3) == 0) {
        int E4 = E >> 2;
        dim3 grid((E4 + THREADS - 1) / THREADS, (B + BTILE - 1) / BTILE);
        bcast_vec_kernel<<<grid, THREADS>>>(out, E4, (long long)E, B);
    } else {
        dim3 grid((E + THREADS - 1) / THREADS, B);
        bcast_scalar_kernel<<<grid, THREADS>>>(out, E);
    }
}